// round 3
// baseline (speedup 1.0000x reference)
#include <cuda_runtime.h>
#include <cstdint>

#define BB 2
#define HH 16
#define LLEN 1024
#define DDIM 64
#define RREL 16

typedef unsigned long long ull;

// precomputed low-rank projections: [bh][l][r*4+e]
__device__ float g_u[(size_t)BB * HH * LLEN * 64];
__device__ float g_v[(size_t)BB * HH * LLEN * 64];

__device__ __forceinline__ ull pk2(float x, float y) {
    ull r;
    asm("mov.b64 %0, {%1,%2};" : "=l"(r) : "r"(__float_as_uint(x)), "r"(__float_as_uint(y)));
    return r;
}
__device__ __forceinline__ ull ffma2(ull a, ull b, ull c) {
    ull d;
    asm("fma.rn.f32x2 %0, %1, %2, %3;" : "=l"(d) : "l"(a), "l"(b), "l"(c));
    return d;
}
__device__ __forceinline__ float2 up2(ull p) {
    unsigned lo, hi;
    asm("mov.b64 {%0,%1}, %2;" : "=r"(lo), "=r"(hi) : "l"(p));
    return make_float2(__uint_as_float(lo), __uint_as_float(hi));
}

// ---------------- precompute u = Q@A1, v = K@A2 ----------------
// grid (2,16,32): x=uv, y=lblk(64 rows), z=bh. 256 threads.
__global__ __launch_bounds__(256) void precompute_uv(
    const float* __restrict__ Q, const float* __restrict__ K,
    const float* __restrict__ A1, const float* __restrict__ A2)
{
    __shared__ float As[64 * 68];    // [oc=r*4+e][d], stride 68
    __shared__ float rowS[64 * 64];  // [row][d]
    int uv = blockIdx.x, lblk = blockIdx.y, bh = blockIdx.z, h = bh & 15;
    int tid = threadIdx.x;

    if (uv == 0) {
        for (int t = tid; t < 4096; t += 256) {
            int r = t >> 8, d = (t >> 2) & 63, e = t & 3;
            As[(r * 4 + e) * 68 + d] = A1[(size_t)((r * HH + h) * 64 + d) * 4 + e];
        }
    } else {
        for (int t = tid; t < 4096; t += 256) {
            int r = t >> 8, e = (t >> 6) & 3, d = t & 63;
            As[(r * 4 + e) * 68 + d] = A2[(size_t)((r * HH + h) * 4 + e) * 64 + d];
        }
    }
    const float* src = (uv == 0 ? Q : K) + ((size_t)bh * LLEN + lblk * 64) * 64;
    for (int t = tid; t < 4096; t += 256) rowS[t] = src[t];
    __syncthreads();

    int row = tid >> 2, sub = tid & 3;  // 4 threads per row, 16 oc each
    float acc[16];
#pragma unroll
    for (int c = 0; c < 16; c++) acc[c] = 0.f;

#pragma unroll
    for (int c4 = 0; c4 < 16; c4++) {
        float4 q = *(const float4*)&rowS[row * 64 + c4 * 4];
#pragma unroll
        for (int c = 0; c < 16; c++) {
            int oc = sub * 16 + c;
            float4 a = *(const float4*)&As[oc * 68 + c4 * 4];
            acc[c] += q.x * a.x + q.y * a.y + q.z * a.z + q.w * a.w;
        }
    }
    float* dst = (uv == 0 ? g_u : g_v) +
                 ((size_t)bh * LLEN + lblk * 64 + row) * 64 + sub * 16;
#pragma unroll
    for (int c = 0; c < 16; c += 4)
        *(float4*)(dst + c) = make_float4(acc[c], acc[c + 1], acc[c + 2], acc[c + 3]);
}

// ---------------- main kernel: 128x128 tile, 8x8 microtile ----------------
#define SD 132  // transposed smem row stride (floats)

__global__ __launch_bounds__(256, 2) void relmat_main(
    const float* __restrict__ Q, const float* __restrict__ K,
    const int* __restrict__ ids, float* __restrict__ out)
{
    extern __shared__ float sm[];
    float* Qs = sm;             // [64][SD] transposed: Qs[d][l]
    float* Ks = sm + 64 * SD;   // [64][SD]
    float* us = sm;             // epilogue alias: [128][64]
    float* vs = sm + 8192;

    int bh = blockIdx.z, b = bh >> 4;
    int l0 = blockIdx.y * 128, m0 = blockIdx.x * 128;
    int tid = threadIdx.x, lane = tid & 31, warp = tid >> 5;

    const float* Qb = Q + ((size_t)bh * LLEN + l0) * 64;
    const float* Kb = K + ((size_t)bh * LLEN + m0) * 64;

    // load + transpose (lane spans rows -> STS stride 1, conflict-free)
#pragma unroll
    for (int it = 0; it < 8; it++) {
        int r = lane + 32 * (it & 3);
        int c4 = warp + 8 * (it >> 2);
        float4 q = *(const float4*)(Qb + r * 64 + c4 * 4);
        float4 k = *(const float4*)(Kb + r * 64 + c4 * 4);
        int d = c4 * 4;
        Qs[(d + 0) * SD + r] = q.x; Qs[(d + 1) * SD + r] = q.y;
        Qs[(d + 2) * SD + r] = q.z; Qs[(d + 3) * SD + r] = q.w;
        Ks[(d + 0) * SD + r] = k.x; Ks[(d + 1) * SD + r] = k.y;
        Ks[(d + 2) * SD + r] = k.z; Ks[(d + 3) * SD + r] = k.w;
    }
    __syncthreads();

    int tx = tid & 15, ty = tid >> 4;  // thread tile: l = ty*8+i, m = tx*8+j
    ull acc[8][4];
#pragma unroll
    for (int i = 0; i < 8; i++)
#pragma unroll
        for (int jp = 0; jp < 4; jp++) acc[i][jp] = 0ull;

#pragma unroll 4
    for (int k = 0; k < 64; k++) {
        float4 ka = *(const float4*)&Ks[k * SD + tx * 8];
        float4 kb = *(const float4*)&Ks[k * SD + tx * 8 + 4];
        float4 qa = *(const float4*)&Qs[k * SD + ty * 8];
        float4 qb = *(const float4*)&Qs[k * SD + ty * 8 + 4];
        ull k2[4];
        k2[0] = pk2(ka.x, ka.y); k2[1] = pk2(ka.z, ka.w);
        k2[2] = pk2(kb.x, kb.y); k2[3] = pk2(kb.z, kb.w);
        float qv[8] = {qa.x, qa.y, qa.z, qa.w, qb.x, qb.y, qb.z, qb.w};
#pragma unroll
        for (int i = 0; i < 8; i++) {
            ull qd = pk2(qv[i], qv[i]);
#pragma unroll
            for (int jp = 0; jp < 4; jp++)
                acc[i][jp] = ffma2(qd, k2[jp], acc[i][jp]);
        }
    }
    __syncthreads();

    // stage u/v tiles into (reused) smem
    {
        const float4* ub = (const float4*)(g_u + ((size_t)bh * LLEN + l0) * 64);
        const float4* vb = (const float4*)(g_v + ((size_t)bh * LLEN + m0) * 64);
        float4* usd = (float4*)us;
        float4* vsd = (float4*)vs;
#pragma unroll
        for (int it = 0; it < 8; it++) {
            int idx = tid + 256 * it;  // 2048 float4s
            usd[idx] = ub[idx];
            vsd[idx] = vb[idx];
        }
    }
    __syncthreads();

    const int* idb = ids + ((size_t)b * LLEN + l0) * LLEN + m0;
    float* ob = out + ((size_t)bh * LLEN + l0) * LLEN + m0;

#pragma unroll
    for (int i = 0; i < 8; i++) {
        int li = ty * 8 + i;
        int4 id0 = *(const int4*)(idb + (size_t)li * LLEN + tx * 8);
        int4 id1 = *(const int4*)(idb + (size_t)li * LLEN + tx * 8 + 4);
        int idv[8] = {id0.x, id0.y, id0.z, id0.w, id1.x, id1.y, id1.z, id1.w};
        float res[8];
#pragma unroll
        for (int j = 0; j < 8; j++) {
            int id = idv[j];
            int rc = min(max(id, 0), RREL - 1);
            float4 uu = *(const float4*)&us[li * 64 + rc * 4];
            float4 vv = *(const float4*)&vs[(tx * 8 + j) * 64 + rc * 4];
            float low = uu.x * vv.x + uu.y * vv.y + uu.z * vv.z + uu.w * vv.w;
            float2 bp = up2(acc[i][j >> 1]);
            float basev = (j & 1) ? bp.y : bp.x;
            res[j] = (id >= 0 && id < RREL) ? (basev + low) : 0.f;
        }
        *(float4*)(ob + (size_t)li * LLEN + tx * 8) =
            make_float4(res[0], res[1], res[2], res[3]);
        *(float4*)(ob + (size_t)li * LLEN + tx * 8 + 4) =
            make_float4(res[4], res[5], res[6], res[7]);
    }
}

extern "C" void kernel_launch(void* const* d_in, const int* in_sizes, int n_in,
                              void* d_out, int out_size) {
    const float* Q   = (const float*)d_in[0];
    const float* K   = (const float*)d_in[1];
    const int*   ids = (const int*)d_in[2];
    const float* A1  = (const float*)d_in[3];
    const float* A2  = (const float*)d_in[4];
    float* out = (float*)d_out;

    static int smem_set = 0;
    int dyn = 2 * 64 * SD * sizeof(float);  // 67584 B
    if (!smem_set) {
        cudaFuncSetAttribute(relmat_main, cudaFuncAttributeMaxDynamicSharedMemorySize, dyn);
        smem_set = 1;
    }

    dim3 gpre(2, 16, BB * HH);
    precompute_uv<<<gpre, 256>>>(Q, K, A1, A2);

    dim3 gmain(LLEN / 128, LLEN / 128, BB * HH);
    relmat_main<<<gmain, 256, dyn>>>(Q, K, ids, out);
}

// round 4
// speedup vs baseline: 1.8439x; 1.8439x over previous
#include <cuda_runtime.h>
#include <cuda_bf16.h>
#include <cstdint>

#define BB 2
#define HH 16
#define LLEN 1024
#define RREL 16

typedef unsigned long long ull;

// precomputed low-rank projections, bf16, layout [bh][l][r*4+e]
__device__ __nv_bfloat16 g_u[(size_t)BB * HH * LLEN * 64];
__device__ __nv_bfloat16 g_v[(size_t)BB * HH * LLEN * 64];

__device__ __forceinline__ ull pkdup(float x) {
    ull r;
    asm("mov.b64 %0, {%1,%1};" : "=l"(r) : "r"(__float_as_uint(x)));
    return r;
}
__device__ __forceinline__ ull ffma2(ull a, ull b, ull c) {
    ull d;
    asm("fma.rn.f32x2 %0, %1, %2, %3;" : "=l"(d) : "l"(a), "l"(b), "l"(c));
    return d;
}
__device__ __forceinline__ float2 up2(ull p) {
    unsigned lo, hi;
    asm("mov.b64 {%0,%1}, %2;" : "=r"(lo), "=r"(hi) : "l"(p));
    return make_float2(__uint_as_float(lo), __uint_as_float(hi));
}

// ---------------- precompute u = Q@A1, v = K@A2 (bf16 out) ----------------
// grid (2,8,32): x=uv, y=lblk(128 rows), z=bh. 256 threads = 8 warps.
// warp w computes output cols oc = w*8..w*8+7 for all 128 rows.
__global__ __launch_bounds__(256) void precompute_uv(
    const float* __restrict__ Q, const float* __restrict__ K,
    const float* __restrict__ A1, const float* __restrict__ A2)
{
    __shared__ float rowT[64 * 128];  // [d][row], both accesses row-contiguous per lane
    __shared__ float As_t[64 * 64];   // [d][oc], oc = r*4+e; warp-uniform reads

    int uv = blockIdx.x, lblk = blockIdx.y, bh = blockIdx.z, h = bh & 15;
    int tid = threadIdx.x, lane = tid & 31, w = tid >> 5;

    // A slice -> As_t[d][oc]
    for (int t = tid; t < 4096; t += 256) {
        int d = t >> 6, oc = t & 63, r = oc >> 2, e = oc & 3;
        float a = (uv == 0)
            ? A1[(size_t)(((r * HH + h) * 64 + d) * 4) + e]
            : A2[(size_t)(((r * HH + h) * 4 + e) * 64) + d];
        As_t[d * 64 + oc] = a;
    }
    // rows -> rowT transposed (lanes span rows: conflict-free STS)
    const float* src = (uv == 0 ? Q : K) + ((size_t)bh * LLEN + lblk * 128) * 64;
    for (int it = 0; it < 8; it++) {
        int idx = tid + 256 * it;          // [0,2048): 128 rows x 16 col-quads
        int row = idx & 127, c4 = idx >> 7;
        float4 q = *(const float4*)(src + (size_t)row * 64 + c4 * 4);
        rowT[(c4 * 4 + 0) * 128 + row] = q.x;
        rowT[(c4 * 4 + 1) * 128 + row] = q.y;
        rowT[(c4 * 4 + 2) * 128 + row] = q.z;
        rowT[(c4 * 4 + 3) * 128 + row] = q.w;
    }
    __syncthreads();

    ull acc[4][4];  // [ri][ocpair]
#pragma unroll
    for (int i = 0; i < 4; i++)
#pragma unroll
        for (int p = 0; p < 4; p++) acc[i][p] = 0ull;

#pragma unroll 4
    for (int d = 0; d < 64; d++) {
        ulonglong2 a01 = *(const ulonglong2*)&As_t[d * 64 + w * 8];      // oc pairs 0-3
        ulonglong2 a23 = *(const ulonglong2*)&As_t[d * 64 + w * 8 + 4];  // oc pairs 4-7
#pragma unroll
        for (int ri = 0; ri < 4; ri++) {
            float q = rowT[d * 128 + lane + 32 * ri];
            ull qd = pkdup(q);
            acc[ri][0] = ffma2(qd, a01.x, acc[ri][0]);
            acc[ri][1] = ffma2(qd, a01.y, acc[ri][1]);
            acc[ri][2] = ffma2(qd, a23.x, acc[ri][2]);
            acc[ri][3] = ffma2(qd, a23.y, acc[ri][3]);
        }
    }

    __nv_bfloat16* dst = (uv == 0 ? g_u : g_v) + ((size_t)bh * LLEN + lblk * 128) * 64;
#pragma unroll
    for (int ri = 0; ri < 4; ri++) {
        int row = lane + 32 * ri;
        unsigned pk[4];
#pragma unroll
        for (int p = 0; p < 4; p++) {
            float2 f = up2(acc[ri][p]);
            __nv_bfloat162 hb = __float22bfloat162_rn(f);
            pk[p] = *(unsigned*)&hb;
        }
        *(uint4*)(dst + (size_t)row * 64 + w * 8) = make_uint4(pk[0], pk[1], pk[2], pk[3]);
    }
}

// ---------------- main kernel: 128x128 tile, 8x8 microtile ----------------
#define SD 132          // transposed fp32 smem row stride
#define UVS 72          // bf16 u/v smem row stride (bank-spreading pad)

__global__ __launch_bounds__(256, 2) void relmat_main(
    const float* __restrict__ Q, const float* __restrict__ K,
    const int* __restrict__ ids, float* __restrict__ out)
{
    extern __shared__ float sm[];
    float* Qs = sm;             // [64][SD] transposed: Qs[d][l]
    float* Ks = sm + 64 * SD;   // [64][SD]
    __nv_bfloat16* us_h = (__nv_bfloat16*)sm;          // epilogue alias [128][UVS]
    __nv_bfloat16* vs_h = us_h + 128 * UVS;

    int bh = blockIdx.z, b = bh >> 4;
    int l0 = blockIdx.y * 128, m0 = blockIdx.x * 128;
    int tid = threadIdx.x, lane = tid & 31, warp = tid >> 5;

    const float* Qb = Q + ((size_t)bh * LLEN + l0) * 64;
    const float* Kb = K + ((size_t)bh * LLEN + m0) * 64;

    // load + transpose (lanes span rows -> conflict-free STS)
#pragma unroll
    for (int it = 0; it < 8; it++) {
        int r = lane + 32 * (it & 3);
        int c4 = warp + 8 * (it >> 2);
        float4 q = *(const float4*)(Qb + (size_t)r * 64 + c4 * 4);
        float4 k = *(const float4*)(Kb + (size_t)r * 64 + c4 * 4);
        int d = c4 * 4;
        Qs[(d + 0) * SD + r] = q.x; Qs[(d + 1) * SD + r] = q.y;
        Qs[(d + 2) * SD + r] = q.z; Qs[(d + 3) * SD + r] = q.w;
        Ks[(d + 0) * SD + r] = k.x; Ks[(d + 1) * SD + r] = k.y;
        Ks[(d + 2) * SD + r] = k.z; Ks[(d + 3) * SD + r] = k.w;
    }
    __syncthreads();

    int tx = tid & 15, ty = tid >> 4;  // l = ty*8+i, m = tx*8+j
    ull acc[8][4];
#pragma unroll
    for (int i = 0; i < 8; i++)
#pragma unroll
        for (int jp = 0; jp < 4; jp++) acc[i][jp] = 0ull;

#pragma unroll 4
    for (int k = 0; k < 64; k++) {
        ulonglong2 ka = *(const ulonglong2*)&Ks[k * SD + tx * 8];      // pairs m0m1,m2m3
        ulonglong2 kb = *(const ulonglong2*)&Ks[k * SD + tx * 8 + 4];  // pairs m4m5,m6m7
        float4 qa = *(const float4*)&Qs[k * SD + ty * 8];
        float4 qb = *(const float4*)&Qs[k * SD + ty * 8 + 4];
        float qv[8] = {qa.x, qa.y, qa.z, qa.w, qb.x, qb.y, qb.z, qb.w};
#pragma unroll
        for (int i = 0; i < 8; i++) {
            ull qd = pkdup(qv[i]);
            acc[i][0] = ffma2(qd, ka.x, acc[i][0]);
            acc[i][1] = ffma2(qd, ka.y, acc[i][1]);
            acc[i][2] = ffma2(qd, kb.x, acc[i][2]);
            acc[i][3] = ffma2(qd, kb.y, acc[i][3]);
        }
    }
    __syncthreads();

    // stage bf16 u/v tiles into reused smem (padded stride UVS)
    {
        const uint4* ub = (const uint4*)(g_u + ((size_t)bh * LLEN + l0) * 64);
        const uint4* vb = (const uint4*)(g_v + ((size_t)bh * LLEN + m0) * 64);
#pragma unroll
        for (int it = 0; it < 8; it++) {
            int idx = tid + 256 * it;             // [0,2048)
            int mat = idx >> 10, rr = (idx >> 3) & 127, cc = idx & 7;
            uint4 val = (mat ? vb : ub)[rr * 8 + cc];
            __nv_bfloat16* dstp = (mat ? vs_h : us_h) + rr * UVS + cc * 8;
            *(uint4*)dstp = val;
        }
    }
    __syncthreads();

    const int* idb = ids + ((size_t)b * LLEN + l0) * LLEN + m0;
    float* ob = out + ((size_t)bh * LLEN + l0) * LLEN + m0;

#pragma unroll
    for (int i = 0; i < 8; i++) {
        int li = ty * 8 + i;
        int4 id0 = *(const int4*)(idb + (size_t)li * LLEN + tx * 8);
        int4 id1 = *(const int4*)(idb + (size_t)li * LLEN + tx * 8 + 4);
        int idv[8] = {id0.x, id0.y, id0.z, id0.w, id1.x, id1.y, id1.z, id1.w};
        float res[8];
#pragma unroll
        for (int j = 0; j < 8; j++) {
            int id = idv[j];
            int rc = min(max(id, 0), RREL - 1);
            uint2 up = *(const uint2*)(us_h + li * UVS + rc * 4);
            uint2 vp = *(const uint2*)(vs_h + (tx * 8 + j) * UVS + rc * 4);
            __nv_bfloat162 u01 = *(__nv_bfloat162*)&up.x;
            __nv_bfloat162 u23 = *(__nv_bfloat162*)&up.y;
            __nv_bfloat162 v01 = *(__nv_bfloat162*)&vp.x;
            __nv_bfloat162 v23 = *(__nv_bfloat162*)&vp.y;
            __nv_bfloat162 prod = __hmul2(u01, v01);
            prod = __hfma2(u23, v23, prod);
            float low = __low2float(prod) + __high2float(prod);
            float2 bp = up2(acc[i][j >> 1]);
            float basev = (j & 1) ? bp.y : bp.x;
            res[j] = (id >= 0 && id < RREL) ? (basev + low) : 0.f;
        }
        *(float4*)(ob + (size_t)li * LLEN + tx * 8) =
            make_float4(res[0], res[1], res[2], res[3]);
        *(float4*)(ob + (size_t)li * LLEN + tx * 8 + 4) =
            make_float4(res[4], res[5], res[6], res[7]);
    }
}

extern "C" void kernel_launch(void* const* d_in, const int* in_sizes, int n_in,
                              void* d_out, int out_size) {
    const float* Q   = (const float*)d_in[0];
    const float* K   = (const float*)d_in[1];
    const int*   ids = (const int*)d_in[2];
    const float* A1  = (const float*)d_in[3];
    const float* A2  = (const float*)d_in[4];
    float* out = (float*)d_out;

    static int smem_set = 0;
    int dyn = 2 * 64 * SD * sizeof(float);  // 67584 B
    if (!smem_set) {
        cudaFuncSetAttribute(relmat_main, cudaFuncAttributeMaxDynamicSharedMemorySize, dyn);
        smem_set = 1;
    }

    dim3 gpre(2, 8, BB * HH);
    precompute_uv<<<gpre, 256>>>(Q, K, A1, A2);

    dim3 gmain(LLEN / 128, LLEN / 128, BB * HH);
    relmat_main<<<gmain, 256, dyn>>>(Q, K, ids, out);
}

// round 6
// speedup vs baseline: 2.6316x; 1.4272x over previous
#include <cuda_runtime.h>
#include <cuda_bf16.h>
#include <cstdint>

#define BB 2
#define HH 16
#define LLEN 1024
#define RREL 16

typedef unsigned long long ull;

// precomputed low-rank projections, bf16, layout [bh][l][r*4+e]
__device__ __nv_bfloat16 g_u[(size_t)BB * HH * LLEN * 64];
__device__ __nv_bfloat16 g_v[(size_t)BB * HH * LLEN * 64];

// ---------------- helpers ----------------
__device__ __forceinline__ ull pkdup(float x) {
    ull r;
    asm("mov.b64 %0, {%1,%1};" : "=l"(r) : "r"(__float_as_uint(x)));
    return r;
}
__device__ __forceinline__ ull ffma2f(ull a, ull b, ull c) {
    ull d;
    asm("fma.rn.f32x2 %0, %1, %2, %3;" : "=l"(d) : "l"(a), "l"(b), "l"(c));
    return d;
}
__device__ __forceinline__ float2 up2(ull p) {
    unsigned lo, hi;
    asm("mov.b64 {%0,%1}, %2;" : "=r"(lo), "=r"(hi) : "l"(p));
    return make_float2(__uint_as_float(lo), __uint_as_float(hi));
}
__device__ __forceinline__ uint32_t smem_u32(const void* p) {
    uint32_t a;
    asm("{ .reg .u64 t; cvta.to.shared.u64 t, %1; cvt.u32.u64 %0, t; }" : "=r"(a) : "l"(p));
    return a;
}
#define SWZ(off) ((off) ^ (((off) >> 3) & 0x70))

__device__ __forceinline__ void ldmx4(uint32_t* r, uint32_t addr) {
    asm volatile("ldmatrix.sync.aligned.m8n8.x4.shared.b16 {%0,%1,%2,%3}, [%4];"
                 : "=r"(r[0]), "=r"(r[1]), "=r"(r[2]), "=r"(r[3]) : "r"(addr));
}
__device__ __forceinline__ void mma16816(float* c, const uint32_t* a,
                                         uint32_t b0, uint32_t b1) {
    asm volatile(
        "mma.sync.aligned.m16n8k16.row.col.f32.bf16.bf16.f32 "
        "{%0,%1,%2,%3}, {%4,%5,%6,%7}, {%8,%9}, {%0,%1,%2,%3};"
        : "+f"(c[0]), "+f"(c[1]), "+f"(c[2]), "+f"(c[3])
        : "r"(a[0]), "r"(a[1]), "r"(a[2]), "r"(a[3]), "r"(b0), "r"(b1));
}

// ---------------- precompute u = Q@A1, v = K@A2 (bf16 out) ----------------
__global__ __launch_bounds__(256) void precompute_uv(
    const float* __restrict__ Q, const float* __restrict__ K,
    const float* __restrict__ A1, const float* __restrict__ A2)
{
    __shared__ float rowT[64 * 128];   // [d][row]
    __shared__ float As_t[64 * 68];    // [d][oc] padded, oc = r*4+e

    int uv = blockIdx.x, lblk = blockIdx.y, bh = blockIdx.z, h = bh & 15;
    int tid = threadIdx.x, lane = tid & 31, w = tid >> 5;

    for (int t = tid; t < 4096; t += 256) {
        int r = t >> 8, rem = t & 255;
        int d, e;
        float a;
        if (uv == 0) { d = rem >> 2; e = rem & 3; a = A1[(size_t)(r * HH + h) * 256 + rem]; }
        else         { e = rem >> 6; d = rem & 63; a = A2[(size_t)(r * HH + h) * 256 + rem]; }
        As_t[d * 68 + r * 4 + e] = a;
    }
    const float* src = (uv == 0 ? Q : K) + ((size_t)bh * LLEN + lblk * 128) * 64;
    for (int it = 0; it < 8; it++) {
        int idx = tid + 256 * it;
        int row = idx & 127, c4 = idx >> 7;
        float4 q = *(const float4*)(src + (size_t)row * 64 + c4 * 4);
        rowT[(c4 * 4 + 0) * 128 + row] = q.x;
        rowT[(c4 * 4 + 1) * 128 + row] = q.y;
        rowT[(c4 * 4 + 2) * 128 + row] = q.z;
        rowT[(c4 * 4 + 3) * 128 + row] = q.w;
    }
    __syncthreads();

    ull acc[4][4];
#pragma unroll
    for (int i = 0; i < 4; i++)
#pragma unroll
        for (int p = 0; p < 4; p++) acc[i][p] = 0ull;

#pragma unroll 4
    for (int d = 0; d < 64; d++) {
        ulonglong2 a01 = *(const ulonglong2*)&As_t[d * 68 + w * 8];
        ulonglong2 a23 = *(const ulonglong2*)&As_t[d * 68 + w * 8 + 4];
#pragma unroll
        for (int ri = 0; ri < 4; ri++) {
            ull qd = pkdup(rowT[d * 128 + lane + 32 * ri]);
            acc[ri][0] = ffma2f(qd, a01.x, acc[ri][0]);
            acc[ri][1] = ffma2f(qd, a01.y, acc[ri][1]);
            acc[ri][2] = ffma2f(qd, a23.x, acc[ri][2]);
            acc[ri][3] = ffma2f(qd, a23.y, acc[ri][3]);
        }
    }

    __nv_bfloat16* dst = (uv == 0 ? g_u : g_v) + ((size_t)bh * LLEN + lblk * 128) * 64;
#pragma unroll
    for (int ri = 0; ri < 4; ri++) {
        int row = lane + 32 * ri;
        unsigned pk[4];
#pragma unroll
        for (int p = 0; p < 4; p++) {
            float2 f = up2(acc[ri][p]);
            __nv_bfloat162 hb = __float22bfloat162_rn(f);
            pk[p] = *(unsigned*)&hb;
        }
        *(uint4*)(dst + (size_t)row * 64 + w * 8) = make_uint4(pk[0], pk[1], pk[2], pk[3]);
    }
}

// ---------------- main kernel: mma.sync bf16-split GEMM + gathered epilogue ----------------
// smem (64 KB dynamic):
//   phase 1 (GEMM): QHI[0,16K) QLO[16K,32K) KHI[32K,48K) KLO[48K,64K)  (SW128 bf16 tiles)
//   phase 2 (epi):  us bf16[128][72] @0 (18432 B), vs @18432
#define SM_QHI 0
#define SM_QLO 16384
#define SM_KHI 32768
#define SM_KLO 49152
#define DYN_SMEM 65536
#define UVS 72

__global__ __launch_bounds__(256, 2) void relmat_main(
    const float* __restrict__ Q, const float* __restrict__ K,
    const int* __restrict__ ids, float* __restrict__ out)
{
    extern __shared__ char sm8[];
    uint32_t sb = smem_u32(sm8);
    __nv_bfloat16* us_h = (__nv_bfloat16*)(sm8);
    __nv_bfloat16* vs_h = (__nv_bfloat16*)(sm8 + 128 * UVS * 2);

    int bh = blockIdx.z, b = bh >> 4;
    int l0 = blockIdx.y * 128, m0 = blockIdx.x * 128;
    int tid = threadIdx.x, lane = tid & 31, warp = tid >> 5;
    int warp_m = warp & 3, warp_n = warp >> 2;   // 4 x 2 warp grid, warp tile 32x64

    // ---- phase 1: load Q/K fp32, split bf16 hi/lo, store swizzled ----
    const float* Qb = Q + ((size_t)bh * LLEN + l0) * 64;
    const float* Kb = K + ((size_t)bh * LLEN + m0) * 64;
#pragma unroll
    for (int it = 0; it < 8; it++) {
        int idx = tid + 256 * it;
        int row = idx >> 4, c4 = idx & 15;
        uint32_t off = SWZ((uint32_t)(row * 128 + c4 * 8));
#pragma unroll
        for (int qk = 0; qk < 2; qk++) {
            const float* srcp = (qk ? Kb : Qb) + (size_t)row * 64 + c4 * 4;
            float4 v = *(const float4*)srcp;
            __nv_bfloat162 h0 = __float22bfloat162_rn(make_float2(v.x, v.y));
            __nv_bfloat162 h1 = __float22bfloat162_rn(make_float2(v.z, v.w));
            float2 r0 = make_float2(v.x - __bfloat162float(__low2bfloat16(h0)),
                                    v.y - __bfloat162float(__high2bfloat16(h0)));
            float2 r1 = make_float2(v.z - __bfloat162float(__low2bfloat16(h1)),
                                    v.w - __bfloat162float(__high2bfloat16(h1)));
            __nv_bfloat162 g0 = __float22bfloat162_rn(r0);
            __nv_bfloat162 g1 = __float22bfloat162_rn(r1);
            char* hi = sm8 + (qk ? SM_KHI : SM_QHI) + off;
            char* lo = sm8 + (qk ? SM_KLO : SM_QLO) + off;
            *(uint2*)hi = make_uint2(*(unsigned*)&h0, *(unsigned*)&h1);
            *(uint2*)lo = make_uint2(*(unsigned*)&g0, *(unsigned*)&g1);
        }
    }
    __syncthreads();

    // ---- phase 2: GEMM via mma.sync, 3 passes fused per k-step ----
    float C[2][8][4];
#pragma unroll
    for (int mt = 0; mt < 2; mt++)
#pragma unroll
        for (int nt = 0; nt < 8; nt++)
#pragma unroll
            for (int q = 0; q < 4; q++) C[mt][nt][q] = 0.f;

    int lrowA = warp_m * 32 + (lane & 15);
    int lrowB = warp_n * 64 + (lane & 15);
    int kb = (lane >> 4);  // 0/1: k-seg within k16 step

#pragma unroll
    for (int ks = 0; ks < 4; ks++) {
        uint32_t kcol = (uint32_t)((ks * 2 + kb) * 16);
        uint32_t ah[2][4], al[2][4];
#pragma unroll
        for (int mt = 0; mt < 2; mt++) {
            uint32_t aoff = SWZ((uint32_t)((lrowA + mt * 16) * 128) + kcol);
            ldmx4(ah[mt], sb + SM_QHI + aoff);
            ldmx4(al[mt], sb + SM_QLO + aoff);
        }
#pragma unroll
        for (int ntp = 0; ntp < 4; ntp++) {
            uint32_t boff = SWZ((uint32_t)((lrowB + ntp * 16) * 128) + kcol);
            uint32_t bhf[4], blf[4];
            ldmx4(bhf, sb + SM_KHI + boff);
            ldmx4(blf, sb + SM_KLO + boff);
#pragma unroll
            for (int mt = 0; mt < 2; mt++)
#pragma unroll
                for (int hv = 0; hv < 2; hv++) {
                    int nt = ntp * 2 + hv;
                    mma16816(C[mt][nt], ah[mt], bhf[hv], bhf[2 + hv]);   // hi*hi
                    mma16816(C[mt][nt], ah[mt], blf[hv], blf[2 + hv]);   // hi*lo
                    mma16816(C[mt][nt], al[mt], bhf[hv], bhf[2 + hv]);   // lo*hi
                }
        }
    }
    __syncthreads();

    // ---- phase 3: stage bf16 u/v tiles into aliased smem ----
    {
        const uint4* ub = (const uint4*)(g_u + ((size_t)bh * LLEN + l0) * 64);
        const uint4* vb = (const uint4*)(g_v + ((size_t)bh * LLEN + m0) * 64);
#pragma unroll
        for (int it = 0; it < 8; it++) {
            int idx = tid + 256 * it;  // [0,2048)
            int mat = idx >> 10, rr = (idx >> 3) & 127, cc = idx & 7;
            uint4 val = (mat ? vb : ub)[rr * 8 + cc];
            __nv_bfloat16* dstp = (mat ? vs_h : us_h) + rr * UVS + cc * 8;
            *(uint4*)dstp = val;
        }
    }
    __syncthreads();

    // ---- phase 4: fragment-direct epilogue ----
    const int* idb = ids + ((size_t)b * LLEN + l0) * LLEN + m0;
    float* ob = out + ((size_t)bh * LLEN + l0) * LLEN + m0;
    int lr = lane >> 2, lc = 2 * (lane & 3);

#pragma unroll
    for (int mt = 0; mt < 2; mt++) {
#pragma unroll
        for (int rh = 0; rh < 2; rh++) {
            int lrow = warp_m * 32 + mt * 16 + rh * 8 + lr;
            const __nv_bfloat16* urow = us_h + lrow * UVS;
            const int* idrow = idb + (size_t)lrow * LLEN;
            float* orow = ob + (size_t)lrow * LLEN;
#pragma unroll
            for (int nt = 0; nt < 8; nt++) {
                int mcol = warp_n * 64 + nt * 8 + lc;
                int2 idp = *(const int2*)(idrow + mcol);
                float res[2];
#pragma unroll
                for (int cc = 0; cc < 2; cc++) {
                    int id = cc ? idp.y : idp.x;
                    int rc = min(max(id, 0), RREL - 1);
                    uint2 up = *(const uint2*)(urow + rc * 4);
                    uint2 vp = *(const uint2*)(vs_h + (mcol + cc) * UVS + rc * 4);
                    __nv_bfloat162 u01 = *(__nv_bfloat162*)&up.x;
                    __nv_bfloat162 u23 = *(__nv_bfloat162*)&up.y;
                    __nv_bfloat162 v01 = *(__nv_bfloat162*)&vp.x;
                    __nv_bfloat162 v23 = *(__nv_bfloat162*)&vp.y;
                    __nv_bfloat162 prod = __hmul2(u01, v01);
                    prod = __hfma2(u23, v23, prod);
                    float low = __low2float(prod) + __high2float(prod);
                    float basev = C[mt][nt][rh * 2 + cc];
                    res[cc] = (id >= 0 && id < RREL) ? (basev + low) : 0.f;
                }
                *(float2*)(orow + mcol) = make_float2(res[0], res[1]);
            }
        }
    }
}

extern "C" void kernel_launch(void* const* d_in, const int* in_sizes, int n_in,
                              void* d_out, int out_size) {
    const float* Q   = (const float*)d_in[0];
    const float* K   = (const float*)d_in[1];
    const int*   ids = (const int*)d_in[2];
    const float* A1  = (const float*)d_in[3];
    const float* A2  = (const float*)d_in[4];
    float* out = (float*)d_out;

    static int once = 0;
    if (!once) {
        cudaFuncSetAttribute(relmat_main, cudaFuncAttributeMaxDynamicSharedMemorySize, DYN_SMEM);
        once = 1;
    }

    dim3 gpre(2, 8, BB * HH);
    precompute_uv<<<gpre, 256>>>(Q, K, A1, A2);

    dim3 gmain(LLEN / 128, LLEN / 128, BB * HH);
    relmat_main<<<gmain, 256, DYN_SMEM>>>(Q, K, ids, out);
}

// round 8
// speedup vs baseline: 2.9761x; 1.1309x over previous
#include <cuda_runtime.h>
#include <cuda_bf16.h>
#include <cstdint>

#define BB 2
#define HH 16
#define LLEN 1024
#define RREL 16

typedef unsigned long long ull;

// precomputed low-rank projections, bf16, layout [bh][l][r*4+e]
__device__ __nv_bfloat16 g_u[(size_t)BB * HH * LLEN * 64];
__device__ __nv_bfloat16 g_v[(size_t)BB * HH * LLEN * 64];

// ---------------- helpers ----------------
__device__ __forceinline__ ull pkdup(float x) {
    ull r;
    asm("mov.b64 %0, {%1,%1};" : "=l"(r) : "r"(__float_as_uint(x)));
    return r;
}
__device__ __forceinline__ ull ffma2f(ull a, ull b, ull c) {
    ull d;
    asm("fma.rn.f32x2 %0, %1, %2, %3;" : "=l"(d) : "l"(a), "l"(b), "l"(c));
    return d;
}
__device__ __forceinline__ float2 up2(ull p) {
    unsigned lo, hi;
    asm("mov.b64 {%0,%1}, %2;" : "=r"(lo), "=r"(hi) : "l"(p));
    return make_float2(__uint_as_float(lo), __uint_as_float(hi));
}
__device__ __forceinline__ uint32_t smem_u32(const void* p) {
    uint32_t a;
    asm("{ .reg .u64 t; cvta.to.shared.u64 t, %1; cvt.u32.u64 %0, t; }" : "=r"(a) : "l"(p));
    return a;
}
#define SWZ(off) ((off) ^ (((off) >> 3) & 0x70))

__device__ __forceinline__ void ldmx4(uint32_t* r, uint32_t addr) {
    asm volatile("ldmatrix.sync.aligned.m8n8.x4.shared.b16 {%0,%1,%2,%3}, [%4];"
                 : "=r"(r[0]), "=r"(r[1]), "=r"(r[2]), "=r"(r[3]) : "r"(addr));
}
__device__ __forceinline__ void mma16816(float* c, const uint32_t* a,
                                         uint32_t b0, uint32_t b1) {
    asm volatile(
        "mma.sync.aligned.m16n8k16.row.col.f32.bf16.bf16.f32 "
        "{%0,%1,%2,%3}, {%4,%5,%6,%7}, {%8,%9}, {%0,%1,%2,%3};"
        : "+f"(c[0]), "+f"(c[1]), "+f"(c[2]), "+f"(c[3])
        : "r"(a[0]), "r"(a[1]), "r"(a[2]), "r"(a[3]), "r"(b0), "r"(b1));
}

// ---------------- precompute u = Q@A1, v = K@A2 (bf16 out) ----------------
// grid (2,16,32): 64 rows per CTA for better wave balance.
__global__ __launch_bounds__(256) void precompute_uv(
    const float* __restrict__ Q, const float* __restrict__ K,
    const float* __restrict__ A1, const float* __restrict__ A2)
{
    __shared__ float rowT[64 * 64];    // [d][row]
    __shared__ float As_t[64 * 68];    // [d][oc] padded, oc = r*4+e

    int uv = blockIdx.x, lblk = blockIdx.y, bh = blockIdx.z, h = bh & 15;
    int tid = threadIdx.x, lane = tid & 31, w = tid >> 5;

    for (int t = tid; t < 4096; t += 256) {
        int r = t >> 8, rem = t & 255;
        int d, e;
        float a;
        if (uv == 0) { d = rem >> 2; e = rem & 3; a = A1[(size_t)(r * HH + h) * 256 + rem]; }
        else         { e = rem >> 6; d = rem & 63; a = A2[(size_t)(r * HH + h) * 256 + rem]; }
        As_t[d * 68 + r * 4 + e] = a;
    }
    const float* src = (uv == 0 ? Q : K) + ((size_t)bh * LLEN + lblk * 64) * 64;
    for (int it = 0; it < 4; it++) {
        int idx = tid + 256 * it;           // [0,1024): 64 rows x 16 col-quads
        int row = idx & 63, c4 = idx >> 6;
        float4 q = *(const float4*)(src + (size_t)row * 64 + c4 * 4);
        rowT[(c4 * 4 + 0) * 64 + row] = q.x;
        rowT[(c4 * 4 + 1) * 64 + row] = q.y;
        rowT[(c4 * 4 + 2) * 64 + row] = q.z;
        rowT[(c4 * 4 + 3) * 64 + row] = q.w;
    }
    __syncthreads();

    ull acc[2][4];
#pragma unroll
    for (int i = 0; i < 2; i++)
#pragma unroll
        for (int p = 0; p < 4; p++) acc[i][p] = 0ull;

#pragma unroll 4
    for (int d = 0; d < 64; d++) {
        ulonglong2 a01 = *(const ulonglong2*)&As_t[d * 68 + w * 8];
        ulonglong2 a23 = *(const ulonglong2*)&As_t[d * 68 + w * 8 + 4];
#pragma unroll
        for (int ri = 0; ri < 2; ri++) {
            ull qd = pkdup(rowT[d * 64 + lane + 32 * ri]);
            acc[ri][0] = ffma2f(qd, a01.x, acc[ri][0]);
            acc[ri][1] = ffma2f(qd, a01.y, acc[ri][1]);
            acc[ri][2] = ffma2f(qd, a23.x, acc[ri][2]);
            acc[ri][3] = ffma2f(qd, a23.y, acc[ri][3]);
        }
    }

    __nv_bfloat16* dst = (uv == 0 ? g_u : g_v) + ((size_t)bh * LLEN + lblk * 64) * 64;
#pragma unroll
    for (int ri = 0; ri < 2; ri++) {
        int row = lane + 32 * ri;
        unsigned pk[4];
#pragma unroll
        for (int p = 0; p < 4; p++) {
            float2 f = up2(acc[ri][p]);
            __nv_bfloat162 hb = __float22bfloat162_rn(f);
            pk[p] = *(unsigned*)&hb;
        }
        *(uint4*)(dst + (size_t)row * 64 + w * 8) = make_uint4(pk[0], pk[1], pk[2], pk[3]);
    }
}

// ---------------- main kernel ----------------
// smem (104448 B dynamic):
//   us bf16[128][72] @ 0        (18432)
//   vs bf16[128][72] @ 18432    (18432)
//   tiles @ 38912: QHI(16K) QLO KHI KLO  (64K)   [GEMM phase]
//   D_s fp32[128][128] slot-swizzled @ 38912     [epilogue, aliases tiles]
#define UVS 72
#define SM_VSOFF 18432
#define SM_TB 38912
#define SM_QHI (SM_TB + 0)
#define SM_QLO (SM_TB + 16384)
#define SM_KHI (SM_TB + 32768)
#define SM_KLO (SM_TB + 49152)
#define DYN_SMEM (SM_TB + 65536)

__global__ __launch_bounds__(256, 2) void relmat_main(
    const float* __restrict__ Q, const float* __restrict__ K,
    const int* __restrict__ ids, float* __restrict__ out)
{
    extern __shared__ char sm8[];
    uint32_t sb = smem_u32(sm8);
    __nv_bfloat16* us_h = (__nv_bfloat16*)(sm8);
    __nv_bfloat16* vs_h = (__nv_bfloat16*)(sm8 + SM_VSOFF);
    float* D_s = (float*)(sm8 + SM_TB);

    int bh = blockIdx.z, b = bh >> 4;
    int l0 = blockIdx.y * 128, m0 = blockIdx.x * 128;
    int tid = threadIdx.x, lane = tid & 31, warp = tid >> 5;
    int warp_m = warp & 3, warp_n = warp >> 2;   // 4x2 warp grid, warp tile 32x64

    // ---- phase 1: stage u/v, and load Q/K fp32 -> split bf16 hi/lo swizzled ----
    {
        const uint4* ub = (const uint4*)(g_u + ((size_t)bh * LLEN + l0) * 64);
        const uint4* vb = (const uint4*)(g_v + ((size_t)bh * LLEN + m0) * 64);
#pragma unroll
        for (int it = 0; it < 8; it++) {
            int idx = tid + 256 * it;  // [0,2048)
            int mat = idx >> 10, rr = (idx >> 3) & 127, cc = idx & 7;
            uint4 val = (mat ? vb : ub)[rr * 8 + cc];
            __nv_bfloat16* dstp = (mat ? vs_h : us_h) + rr * UVS + cc * 8;
            *(uint4*)dstp = val;
        }
    }
    const float* Qb = Q + ((size_t)bh * LLEN + l0) * 64;
    const float* Kb = K + ((size_t)bh * LLEN + m0) * 64;
#pragma unroll
    for (int it = 0; it < 8; it++) {
        int idx = tid + 256 * it;
        int row = idx >> 4, c4 = idx & 15;
        uint32_t off = SWZ((uint32_t)(row * 128 + c4 * 8));
#pragma unroll
        for (int qk = 0; qk < 2; qk++) {
            const float* srcp = (qk ? Kb : Qb) + (size_t)row * 64 + c4 * 4;
            float4 v = *(const float4*)srcp;
            __nv_bfloat162 h0 = __float22bfloat162_rn(make_float2(v.x, v.y));
            __nv_bfloat162 h1 = __float22bfloat162_rn(make_float2(v.z, v.w));
            float2 r0 = make_float2(v.x - __bfloat162float(__low2bfloat16(h0)),
                                    v.y - __bfloat162float(__high2bfloat16(h0)));
            float2 r1 = make_float2(v.z - __bfloat162float(__low2bfloat16(h1)),
                                    v.w - __bfloat162float(__high2bfloat16(h1)));
            __nv_bfloat162 g0 = __float22bfloat162_rn(r0);
            __nv_bfloat162 g1 = __float22bfloat162_rn(r1);
            char* hi = sm8 + (qk ? SM_KHI : SM_QHI) + off;
            char* lo = sm8 + (qk ? SM_KLO : SM_QLO) + off;
            *(uint2*)hi = make_uint2(*(unsigned*)&h0, *(unsigned*)&h1);
            *(uint2*)lo = make_uint2(*(unsigned*)&g0, *(unsigned*)&g1);
        }
    }
    __syncthreads();

    // ---- phase 2: GEMM, 3 bf16-split passes fused per k-step ----
    float C[2][8][4];
#pragma unroll
    for (int mt = 0; mt < 2; mt++)
#pragma unroll
        for (int nt = 0; nt < 8; nt++)
#pragma unroll
            for (int q = 0; q < 4; q++) C[mt][nt][q] = 0.f;

    int lrowA = warp_m * 32 + (lane & 15);
    int lrowB = warp_n * 64 + (lane & 15);
    int kb = (lane >> 4);

#pragma unroll
    for (int ks = 0; ks < 4; ks++) {
        uint32_t kcol = (uint32_t)((ks * 2 + kb) * 16);
        uint32_t ah[2][4], al[2][4];
#pragma unroll
        for (int mt = 0; mt < 2; mt++) {
            uint32_t aoff = SWZ((uint32_t)((lrowA + mt * 16) * 128) + kcol);
            ldmx4(ah[mt], sb + SM_QHI + aoff);
            ldmx4(al[mt], sb + SM_QLO + aoff);
        }
#pragma unroll
        for (int ntp = 0; ntp < 4; ntp++) {
            uint32_t boff = SWZ((uint32_t)((lrowB + ntp * 16) * 128) + kcol);
            uint32_t bhf[4], blf[4];
            ldmx4(bhf, sb + SM_KHI + boff);
            ldmx4(blf, sb + SM_KLO + boff);
#pragma unroll
            for (int mt = 0; mt < 2; mt++)
#pragma unroll
                for (int hv = 0; hv < 2; hv++) {
                    int nt = ntp * 2 + hv;
                    mma16816(C[mt][nt], ah[mt], bhf[hv], bhf[2 + hv]);
                    mma16816(C[mt][nt], ah[mt], blf[hv], blf[2 + hv]);
                    mma16816(C[mt][nt], al[mt], bhf[hv], bhf[2 + hv]);
                }
        }
    }
    __syncthreads();   // all warps done reading tiles before D_s overwrite

    // ---- phase 3: C fragments -> D_s (slot-swizzled, conflict-free) ----
    {
        int lr = lane >> 2, lc2 = 2 * (lane & 3);
#pragma unroll
        for (int mt = 0; mt < 2; mt++)
#pragma unroll
            for (int nt = 0; nt < 8; nt++)
#pragma unroll
                for (int rh = 0; rh < 2; rh++) {
                    int row = warp_m * 32 + mt * 16 + rh * 8 + lr;
                    int cg = warp_n * 8 + nt;
                    int phys = (cg + row) & 15;
                    *(float2*)&D_s[row * 128 + phys * 8 + lc2] =
                        make_float2(C[mt][nt][rh * 2], C[mt][nt][rh * 2 + 1]);
                }
    }
    __syncthreads();

    // ---- phase 4: row-major epilogue ----
    // warp w: rows w*16..w*16+15; lane: cols lane*4..lane*4+3
    const int* idb = ids + ((size_t)b * LLEN + l0) * LLEN + m0;
    float* ob = out + ((size_t)bh * LLEN + l0) * LLEN + m0;
    int cg = lane >> 1, half4 = (lane & 1) * 4;
    const __nv_bfloat16* vbase0 = vs_h + (lane * 4) * UVS;

#pragma unroll 4
    for (int i = 0; i < 16; i++) {
        int row = warp * 16 + i;
        int4 idp = *(const int4*)(idb + (size_t)row * LLEN + lane * 4);
        float4 base4 = *(const float4*)&D_s[row * 128 + ((cg + row) & 15) * 8 + half4];
        const __nv_bfloat16* urow = us_h + row * UVS;
        int idv[4] = {idp.x, idp.y, idp.z, idp.w};
        float basev[4] = {base4.x, base4.y, base4.z, base4.w};
        float res[4];
#pragma unroll
        for (int cc = 0; cc < 4; cc++) {
            int id = idv[cc];
            int rc = min(max(id, 0), RREL - 1);
            uint2 up = *(const uint2*)(urow + rc * 4);
            uint2 vp = *(const uint2*)(vbase0 + cc * UVS + rc * 4);
            __nv_bfloat162 u01 = *(__nv_bfloat162*)&up.x;
            __nv_bfloat162 u23 = *(__nv_bfloat162*)&up.y;
            __nv_bfloat162 v01 = *(__nv_bfloat162*)&vp.x;
            __nv_bfloat162 v23 = *(__nv_bfloat162*)&vp.y;
            __nv_bfloat162 prod = __hmul2(u01, v01);
            prod = __hfma2(u23, v23, prod);
            float low = __low2float(prod) + __high2float(prod);
            res[cc] = ((unsigned)id < RREL) ? (basev[cc] + low) : 0.f;
        }
        *(float4*)(ob + (size_t)row * LLEN + lane * 4) =
            make_float4(res[0], res[1], res[2], res[3]);
    }
}

extern "C" void kernel_launch(void* const* d_in, const int* in_sizes, int n_in,
                              void* d_out, int out_size) {
    const float* Q   = (const float*)d_in[0];
    const float* K   = (const float*)d_in[1];
    const int*   ids = (const int*)d_in[2];
    const float* A1  = (const float*)d_in[3];
    const float* A2  = (const float*)d_in[4];
    float* out = (float*)d_out;

    static int once = 0;
    if (!once) {
        cudaFuncSetAttribute(relmat_main, cudaFuncAttributeMaxDynamicSharedMemorySize, DYN_SMEM);
        once = 1;
    }

    dim3 gpre(2, 16, BB * HH);
    precompute_uv<<<gpre, 256>>>(Q, K, A1, A2);

    dim3 gmain(LLEN / 128, LLEN / 128, BB * HH);
    relmat_main<<<gmain, 256, DYN_SMEM>>>(Q, K, ids, out);
}

// round 9
// speedup vs baseline: 3.3179x; 1.1148x over previous
#include <cuda_runtime.h>
#include <cuda_bf16.h>
#include <cstdint>

#define BB 2
#define HH 16
#define LLEN 1024
#define RREL 16

typedef unsigned long long ull;

// precomputed low-rank projections, bf16, layout [bh][l][r*4+e]
__device__ __nv_bfloat16 g_u[(size_t)BB * HH * LLEN * 64];
__device__ __nv_bfloat16 g_v[(size_t)BB * HH * LLEN * 64];

// ---------------- helpers ----------------
__device__ __forceinline__ uint32_t smem_u32(const void* p) {
    uint32_t a;
    asm("{ .reg .u64 t; cvta.to.shared.u64 t, %1; cvt.u32.u64 %0, t; }" : "=r"(a) : "l"(p));
    return a;
}
#define SWZ(off) ((off) ^ (((off) >> 3) & 0x70))

__device__ __forceinline__ void ldmx4(uint32_t* r, uint32_t addr) {
    asm volatile("ldmatrix.sync.aligned.m8n8.x4.shared.b16 {%0,%1,%2,%3}, [%4];"
                 : "=r"(r[0]), "=r"(r[1]), "=r"(r[2]), "=r"(r[3]) : "r"(addr));
}
__device__ __forceinline__ void mma16816(float* c, const uint32_t* a,
                                         uint32_t b0, uint32_t b1) {
    asm volatile(
        "mma.sync.aligned.m16n8k16.row.col.f32.bf16.bf16.f32 "
        "{%0,%1,%2,%3}, {%4,%5,%6,%7}, {%8,%9}, {%0,%1,%2,%3};"
        : "+f"(c[0]), "+f"(c[1]), "+f"(c[2]), "+f"(c[3])
        : "r"(a[0]), "r"(a[1]), "r"(a[2]), "r"(a[3]), "r"(b0), "r"(b1));
}
__device__ __forceinline__ unsigned bf2pack(float x, float y) {
    __nv_bfloat162 h = __float22bfloat162_rn(make_float2(x, y));
    return *(unsigned*)&h;
}

// ---------------- precompute via mma: u = Q@A1, v = K@A2 (bf16) ----------------
// grid (2,8,32): x=uv, y=lblk(128 rows), z=bh. 256 threads = 8 warps.
// C[128x64] = Row[128x64] @ A_t[64(oc) x 64(d)]^T   (both bf16, SW128 smem)
__global__ __launch_bounds__(256) void precompute_uv_mma(
    const float* __restrict__ Q, const float* __restrict__ K,
    const float* __restrict__ A1, const float* __restrict__ A2)
{
    __shared__ char psm[16384 + 8192];   // Qt[128][64]bf16 @0, As[64][64]bf16 @16384
    uint32_t sb = smem_u32(psm);

    int uv = blockIdx.x, lblk = blockIdx.y, bh = blockIdx.z, h = bh & 15;
    int tid = threadIdx.x, lane = tid & 31, w = tid >> 5;

    // stage A slice -> As[oc][d], bf16, swizzled
    for (int t = tid; t < 4096; t += 256) {
        int r = t >> 8, rem = t & 255;
        int oc, d;
        float a;
        if (uv == 0) { d = rem >> 2; oc = r * 4 + (rem & 3);
                       a = A1[(size_t)(r * HH + h) * 256 + rem]; }
        else         { oc = r * 4 + (rem >> 6); d = rem & 63;
                       a = A2[(size_t)(r * HH + h) * 256 + rem]; }
        *(__nv_bfloat16*)(psm + 16384 + SWZ((uint32_t)(oc * 128 + d * 2))) =
            __float2bfloat16(a);
    }
    // stage row tile (fp32 -> bf16), swizzled
    const float* src = (uv == 0 ? Q : K) + ((size_t)bh * LLEN + lblk * 128) * 64;
#pragma unroll
    for (int it = 0; it < 8; it++) {
        int idx = tid + 256 * it;          // 128 rows x 16 col-quads
        int row = idx >> 4, c4 = idx & 15;
        float4 v = *(const float4*)(src + (size_t)row * 64 + c4 * 4);
        *(uint2*)(psm + SWZ((uint32_t)(row * 128 + c4 * 8))) =
            make_uint2(bf2pack(v.x, v.y), bf2pack(v.z, v.w));
    }
    __syncthreads();

    float C[8][4];
#pragma unroll
    for (int nt = 0; nt < 8; nt++)
#pragma unroll
        for (int q = 0; q < 4; q++) C[nt][q] = 0.f;

    int lrowA = w * 16 + (lane & 15);
    int lrowB = (lane & 15);
    int kb = lane >> 4;

#pragma unroll
    for (int ks = 0; ks < 4; ks++) {
        uint32_t kcol = (uint32_t)((ks * 2 + kb) * 16);
        uint32_t af[4];
        ldmx4(af, sb + SWZ((uint32_t)(lrowA * 128) + kcol));
#pragma unroll
        for (int ntp = 0; ntp < 4; ntp++) {
            uint32_t bf[4];
            ldmx4(bf, sb + 16384 + SWZ((uint32_t)((lrowB + ntp * 16) * 128) + kcol));
#pragma unroll
            for (int hv = 0; hv < 2; hv++)
                mma16816(C[ntp * 2 + hv], af, bf[hv], bf[2 + hv]);
        }
    }

    __nv_bfloat16* dst = (uv == 0 ? g_u : g_v) + ((size_t)bh * LLEN + lblk * 128) * 64;
    int r0 = w * 16 + (lane >> 2), c0 = 2 * (lane & 3);
#pragma unroll
    for (int nt = 0; nt < 8; nt++) {
        *(unsigned*)&dst[(size_t)r0 * 64 + nt * 8 + c0] = bf2pack(C[nt][0], C[nt][1]);
        *(unsigned*)&dst[(size_t)(r0 + 8) * 64 + nt * 8 + c0] = bf2pack(C[nt][2], C[nt][3]);
    }
}

// ---------------- main kernel ----------------
// smem (104448 B dynamic):
//   us  bf16[128][UVS=72] @ 0        (18432)
//   v_t bf16[16][VST=516] @ 18432    (16512)   [rc][m*4+e], stride 1032 B
//   tiles @ 38912: QHI(16K) QLO KHI KLO (64K)  [GEMM phase]
//   D_s fp32[128][128] slot-swizzled @ 38912   [epilogue, aliases tiles]
#define UVS 72
#define VST 516
#define SM_VT 18432
#define SM_TB 38912
#define SM_QHI (SM_TB + 0)
#define SM_QLO (SM_TB + 16384)
#define SM_KHI (SM_TB + 32768)
#define SM_KLO (SM_TB + 49152)
#define DYN_SMEM (SM_TB + 65536)

__global__ __launch_bounds__(256, 2) void relmat_main(
    const float* __restrict__ Q, const float* __restrict__ K,
    const int* __restrict__ ids, float* __restrict__ out)
{
    extern __shared__ char sm8[];
    uint32_t sb = smem_u32(sm8);
    __nv_bfloat16* us_h = (__nv_bfloat16*)(sm8);
    __nv_bfloat16* vs_t = (__nv_bfloat16*)(sm8 + SM_VT);
    float* D_s = (float*)(sm8 + SM_TB);

    int bh = blockIdx.z, b = bh >> 4;
    int l0 = blockIdx.y * 128, m0 = blockIdx.x * 128;
    int tid = threadIdx.x, lane = tid & 31, warp = tid >> 5;
    int warp_m = warp & 3, warp_n = warp >> 2;   // 4x2 warp grid, warp tile 32x64

    // ---- phase 1: stage u (row-major) and v (transposed), load+split Q/K ----
    {
        const uint4* ub = (const uint4*)(g_u + ((size_t)bh * LLEN + l0) * 64);
        const uint4* vb = (const uint4*)(g_v + ((size_t)bh * LLEN + m0) * 64);
#pragma unroll
        for (int it = 0; it < 8; it++) {
            int idx = tid + 256 * it;  // [0,2048)
            int mat = idx >> 10, rr = (idx >> 3) & 127, cc = idx & 7;
            uint4 val = (mat ? vb : ub)[rr * 8 + cc];
            if (mat) {
                // val = v[rr][rc=2cc, e0..3 | rc=2cc+1, e0..3]
                *(uint2*)&vs_t[(2 * cc) * VST + rr * 4]     = make_uint2(val.x, val.y);
                *(uint2*)&vs_t[(2 * cc + 1) * VST + rr * 4] = make_uint2(val.z, val.w);
            } else {
                *(uint4*)(us_h + rr * UVS + cc * 8) = val;
            }
        }
    }
    const float* Qb = Q + ((size_t)bh * LLEN + l0) * 64;
    const float* Kb = K + ((size_t)bh * LLEN + m0) * 64;
#pragma unroll
    for (int it = 0; it < 8; it++) {
        int idx = tid + 256 * it;
        int row = idx >> 4, c4 = idx & 15;
        uint32_t off = SWZ((uint32_t)(row * 128 + c4 * 8));
#pragma unroll
        for (int qk = 0; qk < 2; qk++) {
            const float* srcp = (qk ? Kb : Qb) + (size_t)row * 64 + c4 * 4;
            float4 v = *(const float4*)srcp;
            __nv_bfloat162 h0 = __float22bfloat162_rn(make_float2(v.x, v.y));
            __nv_bfloat162 h1 = __float22bfloat162_rn(make_float2(v.z, v.w));
            float2 r0 = make_float2(v.x - __bfloat162float(__low2bfloat16(h0)),
                                    v.y - __bfloat162float(__high2bfloat16(h0)));
            float2 r1 = make_float2(v.z - __bfloat162float(__low2bfloat16(h1)),
                                    v.w - __bfloat162float(__high2bfloat16(h1)));
            __nv_bfloat162 g0 = __float22bfloat162_rn(r0);
            __nv_bfloat162 g1 = __float22bfloat162_rn(r1);
            char* hi = sm8 + (qk ? SM_KHI : SM_QHI) + off;
            char* lo = sm8 + (qk ? SM_KLO : SM_QLO) + off;
            *(uint2*)hi = make_uint2(*(unsigned*)&h0, *(unsigned*)&h1);
            *(uint2*)lo = make_uint2(*(unsigned*)&g0, *(unsigned*)&g1);
        }
    }
    __syncthreads();

    // ---- phase 2: GEMM, 3 bf16-split passes fused per k-step ----
    float C[2][8][4];
#pragma unroll
    for (int mt = 0; mt < 2; mt++)
#pragma unroll
        for (int nt = 0; nt < 8; nt++)
#pragma unroll
            for (int q = 0; q < 4; q++) C[mt][nt][q] = 0.f;

    int lrowA = warp_m * 32 + (lane & 15);
    int lrowB = warp_n * 64 + (lane & 15);
    int kb = (lane >> 4);

#pragma unroll
    for (int ks = 0; ks < 4; ks++) {
        uint32_t kcol = (uint32_t)((ks * 2 + kb) * 16);
        uint32_t ah[2][4], al[2][4];
#pragma unroll
        for (int mt = 0; mt < 2; mt++) {
            uint32_t aoff = SWZ((uint32_t)((lrowA + mt * 16) * 128) + kcol);
            ldmx4(ah[mt], sb + SM_QHI + aoff);
            ldmx4(al[mt], sb + SM_QLO + aoff);
        }
#pragma unroll
        for (int ntp = 0; ntp < 4; ntp++) {
            uint32_t boff = SWZ((uint32_t)((lrowB + ntp * 16) * 128) + kcol);
            uint32_t bhf[4], blf[4];
            ldmx4(bhf, sb + SM_KHI + boff);
            ldmx4(blf, sb + SM_KLO + boff);
#pragma unroll
            for (int mt = 0; mt < 2; mt++)
#pragma unroll
                for (int hv = 0; hv < 2; hv++) {
                    int nt = ntp * 2 + hv;
                    mma16816(C[mt][nt], ah[mt], bhf[hv], bhf[2 + hv]);
                    mma16816(C[mt][nt], ah[mt], blf[hv], blf[2 + hv]);
                    mma16816(C[mt][nt], al[mt], bhf[hv], bhf[2 + hv]);
                }
        }
    }
    __syncthreads();   // tiles no longer needed; D_s may overwrite

    // ---- phase 3: C fragments -> D_s (slot-swizzled, conflict-free) ----
    {
        int lr = lane >> 2, lc2 = 2 * (lane & 3);
#pragma unroll
        for (int mt = 0; mt < 2; mt++)
#pragma unroll
            for (int nt = 0; nt < 8; nt++)
#pragma unroll
                for (int rh = 0; rh < 2; rh++) {
                    int row = warp_m * 32 + mt * 16 + rh * 8 + lr;
                    int cg = warp_n * 8 + nt;
                    int phys = (cg + row) & 15;
                    *(float2*)&D_s[row * 128 + phys * 8 + lc2] =
                        make_float2(C[mt][nt][rh * 2], C[mt][nt][rh * 2 + 1]);
                }
    }
    __syncthreads();

    // ---- phase 4: row-major epilogue ----
    const int* idb = ids + ((size_t)b * LLEN + l0) * LLEN + m0;
    float* ob = out + ((size_t)bh * LLEN + l0) * LLEN + m0;
    int cg = lane >> 1, half4 = (lane & 1) * 4;
    const __nv_bfloat16* vt0 = vs_t + lane * 16;   // m = lane*4 base (4 elems per m)

#pragma unroll 4
    for (int i = 0; i < 16; i++) {
        int row = warp * 16 + i;
        int4 idp = *(const int4*)(idb + (size_t)row * LLEN + lane * 4);
        float4 base4 = *(const float4*)&D_s[row * 128 + ((cg + row) & 15) * 8 + half4];
        const __nv_bfloat16* urow = us_h + row * UVS;
        int idv[4] = {idp.x, idp.y, idp.z, idp.w};
        float basev[4] = {base4.x, base4.y, base4.z, base4.w};
        float res[4];
#pragma unroll
        for (int cc = 0; cc < 4; cc++) {
            int id = idv[cc];
            int rc = min(max(id, 0), RREL - 1);
            uint2 up = *(const uint2*)(urow + rc * 4);
            uint2 vp = *(const uint2*)(vt0 + rc * VST + cc * 4);
            __nv_bfloat162 u01 = *(__nv_bfloat162*)&up.x;
            __nv_bfloat162 u23 = *(__nv_bfloat162*)&up.y;
            __nv_bfloat162 v01 = *(__nv_bfloat162*)&vp.x;
            __nv_bfloat162 v23 = *(__nv_bfloat162*)&vp.y;
            __nv_bfloat162 prod = __hmul2(u01, v01);
            prod = __hfma2(u23, v23, prod);
            float low = __low2float(prod) + __high2float(prod);
            res[cc] = ((unsigned)id < RREL) ? (basev[cc] + low) : 0.f;
        }
        *(float4*)(ob + (size_t)row * LLEN + lane * 4) =
            make_float4(res[0], res[1], res[2], res[3]);
    }
}

extern "C" void kernel_launch(void* const* d_in, const int* in_sizes, int n_in,
                              void* d_out, int out_size) {
    const float* Q   = (const float*)d_in[0];
    const float* K   = (const float*)d_in[1];
    const int*   ids = (const int*)d_in[2];
    const float* A1  = (const float*)d_in[3];
    const float* A2  = (const float*)d_in[4];
    float* out = (float*)d_out;

    static int once = 0;
    if (!once) {
        cudaFuncSetAttribute(relmat_main, cudaFuncAttributeMaxDynamicSharedMemorySize, DYN_SMEM);
        once = 1;
    }

    dim3 gpre(2, 8, BB * HH);
    precompute_uv_mma<<<gpre, 256>>>(Q, K, A1, A2);

    dim3 gmain(LLEN / 128, LLEN / 128, BB * HH);
    relmat_main<<<gmain, 256, DYN_SMEM>>>(Q, K, ids, out);
}

// round 10
// speedup vs baseline: 3.6593x; 1.1029x over previous
#include <cuda_runtime.h>
#include <cuda_bf16.h>
#include <cuda_fp16.h>
#include <cstdint>

#define BB 2
#define HH 16
#define LLEN 1024
#define RREL 16

typedef unsigned long long ull;

// precomputed low-rank projections, bf16, layout [bh][l][r*4+e]
__device__ __nv_bfloat16 g_u[(size_t)BB * HH * LLEN * 64];
__device__ __nv_bfloat16 g_v[(size_t)BB * HH * LLEN * 64];

// ---------------- helpers ----------------
__device__ __forceinline__ uint32_t smem_u32(const void* p) {
    uint32_t a;
    asm("{ .reg .u64 t; cvta.to.shared.u64 t, %1; cvt.u32.u64 %0, t; }" : "=r"(a) : "l"(p));
    return a;
}
#define SWZ(off) ((off) ^ (((off) >> 3) & 0x70))

__device__ __forceinline__ void ldmx4(uint32_t* r, uint32_t addr) {
    asm volatile("ldmatrix.sync.aligned.m8n8.x4.shared.b16 {%0,%1,%2,%3}, [%4];"
                 : "=r"(r[0]), "=r"(r[1]), "=r"(r[2]), "=r"(r[3]) : "r"(addr));
}
__device__ __forceinline__ void mma16816bf(float* c, const uint32_t* a,
                                           uint32_t b0, uint32_t b1) {
    asm volatile(
        "mma.sync.aligned.m16n8k16.row.col.f32.bf16.bf16.f32 "
        "{%0,%1,%2,%3}, {%4,%5,%6,%7}, {%8,%9}, {%0,%1,%2,%3};"
        : "+f"(c[0]), "+f"(c[1]), "+f"(c[2]), "+f"(c[3])
        : "r"(a[0]), "r"(a[1]), "r"(a[2]), "r"(a[3]), "r"(b0), "r"(b1));
}
__device__ __forceinline__ void mma16816h(float* c, const uint32_t* a,
                                          uint32_t b0, uint32_t b1) {
    asm volatile(
        "mma.sync.aligned.m16n8k16.row.col.f32.f16.f16.f32 "
        "{%0,%1,%2,%3}, {%4,%5,%6,%7}, {%8,%9}, {%0,%1,%2,%3};"
        : "+f"(c[0]), "+f"(c[1]), "+f"(c[2]), "+f"(c[3])
        : "r"(a[0]), "r"(a[1]), "r"(a[2]), "r"(a[3]), "r"(b0), "r"(b1));
}
__device__ __forceinline__ unsigned bf2pack(float x, float y) {
    __nv_bfloat162 h = __float22bfloat162_rn(make_float2(x, y));
    return *(unsigned*)&h;
}
__device__ __forceinline__ unsigned h2pack(float x, float y) {
    __half2 h = __floats2half2_rn(x, y);
    return *(unsigned*)&h;
}

// ---------------- precompute via mma: u = Q@A1, v = K@A2 (bf16) ----------------
__global__ __launch_bounds__(256) void precompute_uv_mma(
    const float* __restrict__ Q, const float* __restrict__ K,
    const float* __restrict__ A1, const float* __restrict__ A2)
{
    __shared__ char psm[16384 + 8192];   // rows[128][64]bf16 @0, As[64][64]bf16 @16384
    uint32_t sb = smem_u32(psm);

    int uv = blockIdx.x, lblk = blockIdx.y, bh = blockIdx.z, h = bh & 15;
    int tid = threadIdx.x, lane = tid & 31, w = tid >> 5;

    for (int t = tid; t < 4096; t += 256) {
        int r = t >> 8, rem = t & 255;
        int oc, d;
        float a;
        if (uv == 0) { d = rem >> 2; oc = r * 4 + (rem & 3);
                       a = A1[(size_t)(r * HH + h) * 256 + rem]; }
        else         { oc = r * 4 + (rem >> 6); d = rem & 63;
                       a = A2[(size_t)(r * HH + h) * 256 + rem]; }
        *(__nv_bfloat16*)(psm + 16384 + SWZ((uint32_t)(oc * 128 + d * 2))) =
            __float2bfloat16(a);
    }
    const float* src = (uv == 0 ? Q : K) + ((size_t)bh * LLEN + lblk * 128) * 64;
#pragma unroll
    for (int it = 0; it < 8; it++) {
        int idx = tid + 256 * it;
        int row = idx >> 4, c4 = idx & 15;
        float4 v = *(const float4*)(src + (size_t)row * 64 + c4 * 4);
        *(uint2*)(psm + SWZ((uint32_t)(row * 128 + c4 * 8))) =
            make_uint2(bf2pack(v.x, v.y), bf2pack(v.z, v.w));
    }
    __syncthreads();

    float C[8][4];
#pragma unroll
    for (int nt = 0; nt < 8; nt++)
#pragma unroll
        for (int q = 0; q < 4; q++) C[nt][q] = 0.f;

    int lrowA = w * 16 + (lane & 15);
    int lrowB = (lane & 15);
    int kb = lane >> 4;

#pragma unroll
    for (int ks = 0; ks < 4; ks++) {
        uint32_t kcol = (uint32_t)((ks * 2 + kb) * 16);
        uint32_t af[4];
        ldmx4(af, sb + SWZ((uint32_t)(lrowA * 128) + kcol));
#pragma unroll
        for (int ntp = 0; ntp < 4; ntp++) {
            uint32_t bf[4];
            ldmx4(bf, sb + 16384 + SWZ((uint32_t)((lrowB + ntp * 16) * 128) + kcol));
#pragma unroll
            for (int hv = 0; hv < 2; hv++)
                mma16816bf(C[ntp * 2 + hv], af, bf[hv], bf[2 + hv]);
        }
    }

    __nv_bfloat16* dst = (uv == 0 ? g_u : g_v) + ((size_t)bh * LLEN + lblk * 128) * 64;
    int r0 = w * 16 + (lane >> 2), c0 = 2 * (lane & 3);
#pragma unroll
    for (int nt = 0; nt < 8; nt++) {
        *(unsigned*)&dst[(size_t)r0 * 64 + nt * 8 + c0] = bf2pack(C[nt][0], C[nt][1]);
        *(unsigned*)&dst[(size_t)(r0 + 8) * 64 + nt * 8 + c0] = bf2pack(C[nt][2], C[nt][3]);
    }
}

// ---------------- main kernel ----------------
// smem (88064 B dynamic):
//   us  bf16[128][UVS=72] @ 0        (18432)
//   v_t bf16[16][VST=516] @ 18432    (16512)
//   tiles @ 38912: QHI(16K) QLO(16K) KHI(16K)  [fp16, GEMM phase]
//   D_s fp32[128][128] slot-swizzled @ 38912   [epilogue, aliases tiles]
#define UVS 72
#define VST 516
#define SM_VT 18432
#define SM_TB 38912
#define SM_QHI (SM_TB + 0)
#define SM_QLO (SM_TB + 16384)
#define SM_KHI (SM_TB + 32768)
#define DYN_SMEM (SM_TB + 65536)   // D_s needs 64K in epilogue phase

__global__ __launch_bounds__(256, 2) void relmat_main(
    const float* __restrict__ Q, const float* __restrict__ K,
    const int* __restrict__ ids, float* __restrict__ out)
{
    extern __shared__ char sm8[];
    uint32_t sb = smem_u32(sm8);
    __nv_bfloat16* us_h = (__nv_bfloat16*)(sm8);
    __nv_bfloat16* vs_t = (__nv_bfloat16*)(sm8 + SM_VT);
    float* D_s = (float*)(sm8 + SM_TB);

    int bh = blockIdx.z, b = bh >> 4;
    int l0 = blockIdx.y * 128, m0 = blockIdx.x * 128;
    int tid = threadIdx.x, lane = tid & 31, warp = tid >> 5;
    int warp_m = warp & 3, warp_n = warp >> 2;   // 4x2 warp grid, warp tile 32x64

    // ---- phase 1: stage u/v; load Q (fp16 hi+lo) and K (fp16 hi) swizzled ----
    {
        const uint4* ub = (const uint4*)(g_u + ((size_t)bh * LLEN + l0) * 64);
        const uint4* vb = (const uint4*)(g_v + ((size_t)bh * LLEN + m0) * 64);
#pragma unroll
        for (int it = 0; it < 8; it++) {
            int idx = tid + 256 * it;
            int mat = idx >> 10, rr = (idx >> 3) & 127, cc = idx & 7;
            uint4 val = (mat ? vb : ub)[rr * 8 + cc];
            if (mat) {
                *(uint2*)&vs_t[(2 * cc) * VST + rr * 4]     = make_uint2(val.x, val.y);
                *(uint2*)&vs_t[(2 * cc + 1) * VST + rr * 4] = make_uint2(val.z, val.w);
            } else {
                *(uint4*)(us_h + rr * UVS + cc * 8) = val;
            }
        }
    }
    const float* Qb = Q + ((size_t)bh * LLEN + l0) * 64;
    const float* Kb = K + ((size_t)bh * LLEN + m0) * 64;
#pragma unroll
    for (int it = 0; it < 8; it++) {
        int idx = tid + 256 * it;
        int row = idx >> 4, c4 = idx & 15;
        uint32_t off = SWZ((uint32_t)(row * 128 + c4 * 8));
        // Q: hi + residual
        {
            float4 v = *(const float4*)(Qb + (size_t)row * 64 + c4 * 4);
            __half2 h0 = __floats2half2_rn(v.x, v.y);
            __half2 h1 = __floats2half2_rn(v.z, v.w);
            float2 r0 = make_float2(v.x - __half2float(__low2half(h0)),
                                    v.y - __half2float(__high2half(h0)));
            float2 r1 = make_float2(v.z - __half2float(__low2half(h1)),
                                    v.w - __half2float(__high2half(h1)));
            *(uint2*)(sm8 + SM_QHI + off) =
                make_uint2(*(unsigned*)&h0, *(unsigned*)&h1);
            *(uint2*)(sm8 + SM_QLO + off) =
                make_uint2(h2pack(r0.x, r0.y), h2pack(r1.x, r1.y));
        }
        // K: hi only
        {
            float4 v = *(const float4*)(Kb + (size_t)row * 64 + c4 * 4);
            *(uint2*)(sm8 + SM_KHI + off) =
                make_uint2(h2pack(v.x, v.y), h2pack(v.z, v.w));
        }
    }
    __syncthreads();

    // ---- phase 2: GEMM, 2 fp16 passes fused per k-step ----
    float C[2][8][4];
#pragma unroll
    for (int mt = 0; mt < 2; mt++)
#pragma unroll
        for (int nt = 0; nt < 8; nt++)
#pragma unroll
            for (int q = 0; q < 4; q++) C[mt][nt][q] = 0.f;

    int lrowA = warp_m * 32 + (lane & 15);
    int lrowB = warp_n * 64 + (lane & 15);
    int kb = (lane >> 4);

#pragma unroll
    for (int ks = 0; ks < 4; ks++) {
        uint32_t kcol = (uint32_t)((ks * 2 + kb) * 16);
        uint32_t ah[2][4], al[2][4];
#pragma unroll
        for (int mt = 0; mt < 2; mt++) {
            uint32_t aoff = SWZ((uint32_t)((lrowA + mt * 16) * 128) + kcol);
            ldmx4(ah[mt], sb + SM_QHI + aoff);
            ldmx4(al[mt], sb + SM_QLO + aoff);
        }
#pragma unroll
        for (int ntp = 0; ntp < 4; ntp++) {
            uint32_t boff = SWZ((uint32_t)((lrowB + ntp * 16) * 128) + kcol);
            uint32_t bhf[4];
            ldmx4(bhf, sb + SM_KHI + boff);
#pragma unroll
            for (int mt = 0; mt < 2; mt++)
#pragma unroll
                for (int hv = 0; hv < 2; hv++) {
                    int nt = ntp * 2 + hv;
                    mma16816h(C[mt][nt], ah[mt], bhf[hv], bhf[2 + hv]);   // qh*kh
                    mma16816h(C[mt][nt], al[mt], bhf[hv], bhf[2 + hv]);   // ql*kh
                }
        }
    }
    __syncthreads();

    // ---- phase 3: C fragments -> D_s (slot-swizzled, conflict-free) ----
    {
        int lr = lane >> 2, lc2 = 2 * (lane & 3);
#pragma unroll
        for (int mt = 0; mt < 2; mt++)
#pragma unroll
            for (int nt = 0; nt < 8; nt++)
#pragma unroll
                for (int rh = 0; rh < 2; rh++) {
                    int row = warp_m * 32 + mt * 16 + rh * 8 + lr;
                    int cg = warp_n * 8 + nt;
                    int phys = (cg + row) & 15;
                    *(float2*)&D_s[row * 128 + phys * 8 + lc2] =
                        make_float2(C[mt][nt][rh * 2], C[mt][nt][rh * 2 + 1]);
                }
    }
    __syncthreads();

    // ---- phase 4: row-major epilogue with ids prefetch ----
    const int* idb = ids + ((size_t)b * LLEN + l0) * LLEN + m0;
    float* ob = out + ((size_t)bh * LLEN + l0) * LLEN + m0;
    int cg = lane >> 1, half4 = (lane & 1) * 4;
    const __nv_bfloat16* vt0 = vs_t + lane * 16;

    int4 idp = *(const int4*)(idb + (size_t)(warp * 16) * LLEN + lane * 4);
#pragma unroll
    for (int i = 0; i < 16; i++) {
        int row = warp * 16 + i;
        int4 idn = (i < 15)
            ? *(const int4*)(idb + (size_t)(row + 1) * LLEN + lane * 4) : idp;
        float4 base4 = *(const float4*)&D_s[row * 128 + ((cg + row) & 15) * 8 + half4];
        const __nv_bfloat16* urow = us_h + row * UVS;
        int idv[4] = {idp.x, idp.y, idp.z, idp.w};
        float basev[4] = {base4.x, base4.y, base4.z, base4.w};
        float res[4];
#pragma unroll
        for (int cc = 0; cc < 4; cc++) {
            int id = idv[cc];
            int rc = min(max(id, 0), RREL - 1);
            uint2 up = *(const uint2*)(urow + rc * 4);
            uint2 vp = *(const uint2*)(vt0 + rc * VST + cc * 4);
            __nv_bfloat162 u01 = *(__nv_bfloat162*)&up.x;
            __nv_bfloat162 u23 = *(__nv_bfloat162*)&up.y;
            __nv_bfloat162 v01 = *(__nv_bfloat162*)&vp.x;
            __nv_bfloat162 v23 = *(__nv_bfloat162*)&vp.y;
            __nv_bfloat162 prod = __hmul2(u01, v01);
            prod = __hfma2(u23, v23, prod);
            float low = __low2float(prod) + __high2float(prod);
            res[cc] = ((unsigned)id < RREL) ? (basev[cc] + low) : 0.f;
        }
        *(float4*)(ob + (size_t)row * LLEN + lane * 4) =
            make_float4(res[0], res[1], res[2], res[3]);
        idp = idn;
    }
}

extern "C" void kernel_launch(void* const* d_in, const int* in_sizes, int n_in,
                              void* d_out, int out_size) {
    const float* Q   = (const float*)d_in[0];
    const float* K   = (const float*)d_in[1];
    const int*   ids = (const int*)d_in[2];
    const float* A1  = (const float*)d_in[3];
    const float* A2  = (const float*)d_in[4];
    float* out = (float*)d_out;

    static int once = 0;
    if (!once) {
        cudaFuncSetAttribute(relmat_main, cudaFuncAttributeMaxDynamicSharedMemorySize, DYN_SMEM);
        once = 1;
    }

    dim3 gpre(2, 8, BB * HH);
    precompute_uv_mma<<<gpre, 256>>>(Q, K, A1, A2);

    dim3 gmain(LLEN / 128, LLEN / 128, BB * HH);
    relmat_main<<<gmain, 256, DYN_SMEM>>>(Q, K, ids, out);
}